// round 3
// baseline (speedup 1.0000x reference)
#include <cuda_runtime.h>

#define TSEQ 2048
#define CH   2048
#define NH   16
#define HD   128

// Scratch (allocation-free rule: __device__ globals)
__device__ float g_q[TSEQ * CH];
__device__ float g_k[TSEQ * CH];
__device__ float g_v[TSEQ * CH];
__device__ float g_o[TSEQ * CH];

// ---------------------------------------------------------------------------
// C[M,N] = A[M,K] @ B[N,K]^T   (M = N = K = 2048, row-major)
// 128x128 block tile, BK=16, 256 threads, 8x8 micro-tile (split quadrants)
// ---------------------------------------------------------------------------
__global__ __launch_bounds__(256) void sgemm_tn(const float* __restrict__ A,
                                                const float* __restrict__ B,
                                                float* __restrict__ C) {
    __shared__ float As[16][129];
    __shared__ float Bs[16][129];

    const int tid = threadIdx.x;
    const int tx = tid & 15;
    const int ty = tid >> 4;
    const int m0 = blockIdx.y * 128;
    const int n0 = blockIdx.x * 128;

    float acc[8][8];
#pragma unroll
    for (int i = 0; i < 8; i++)
#pragma unroll
        for (int j = 0; j < 8; j++) acc[i][j] = 0.f;

    for (int k0 = 0; k0 < CH; k0 += 16) {
#pragma unroll
        for (int l = 0; l < 2; l++) {
            int u   = tid + l * 256;
            int row = u >> 2;
            int c4  = (u & 3) * 4;
            float4 va = *(const float4*)(A + (size_t)(m0 + row) * CH + k0 + c4);
            As[c4 + 0][row] = va.x;
            As[c4 + 1][row] = va.y;
            As[c4 + 2][row] = va.z;
            As[c4 + 3][row] = va.w;
            float4 vb = *(const float4*)(B + (size_t)(n0 + row) * CH + k0 + c4);
            Bs[c4 + 0][row] = vb.x;
            Bs[c4 + 1][row] = vb.y;
            Bs[c4 + 2][row] = vb.z;
            Bs[c4 + 3][row] = vb.w;
        }
        __syncthreads();

#pragma unroll
        for (int kk = 0; kk < 16; kk++) {
            float a[8], b[8];
#pragma unroll
            for (int i = 0; i < 4; i++) {
                a[i]     = As[kk][ty * 4 + i];
                a[i + 4] = As[kk][64 + ty * 4 + i];
                b[i]     = Bs[kk][tx * 4 + i];
                b[i + 4] = Bs[kk][64 + tx * 4 + i];
            }
#pragma unroll
            for (int i = 0; i < 8; i++)
#pragma unroll
                for (int j = 0; j < 8; j++) acc[i][j] += a[i] * b[j];
        }
        __syncthreads();
    }

#pragma unroll
    for (int i = 0; i < 8; i++) {
        int m = m0 + ((i < 4) ? (ty * 4 + i) : (64 + ty * 4 + i - 4));
#pragma unroll
        for (int j = 0; j < 8; j++) {
            int n = n0 + ((j < 4) ? (tx * 4 + j) : (64 + tx * 4 + j - 4));
            C[(size_t)m * CH + n] = acc[i][j];
        }
    }
}

// ---------------------------------------------------------------------------
// ReBased feature map: y = LayerNorm(x * gamma + beta) over D=128 per (t,h)
// row, with optional D^-0.5 scale (for q). One warp per row.
// blockIdx.y == 0 -> g_q (scaled), == 1 -> g_k
// ---------------------------------------------------------------------------
__global__ __launch_bounds__(256) void featmap(const float* __restrict__ gamma,
                                               const float* __restrict__ beta) {
    const int warp = threadIdx.x >> 5;
    const int lane = threadIdx.x & 31;
    const int row  = blockIdx.x * 8 + warp;   // 0 .. T*NH-1
    float* base = (blockIdx.y == 0) ? g_q : g_k;
    const float scale = (blockIdx.y == 0) ? 0.08838834764831845f : 1.0f;  // D^-0.5
    const int t = row >> 4;
    const int h = row & 15;
    float* p = base + (size_t)t * CH + h * HD;

    float x[4];
    float s = 0.f, sq = 0.f;
#pragma unroll
    for (int r = 0; r < 4; r++) {
        int d = lane + 32 * r;
        float y = p[d] * gamma[d] + beta[d];
        x[r] = y;
        s  += y;
        sq += y * y;
    }
#pragma unroll
    for (int o = 16; o; o >>= 1) {
        s  += __shfl_xor_sync(0xFFFFFFFFu, s, o);
        sq += __shfl_xor_sync(0xFFFFFFFFu, sq, o);
    }
    const float mu  = s * (1.0f / HD);
    const float var = sq * (1.0f / HD) - mu * mu;
    const float rs  = rsqrtf(var + 1e-5f) * scale;
#pragma unroll
    for (int r = 0; r < 4; r++) p[lane + 32 * r] = (x[r] - mu) * rs;
}

// ---------------------------------------------------------------------------
// Causal quadratic attention (no softmax):
//   S = (q . k)^2 (causal), O = S @ v, z = rowsum(S), out = O / (z + 1e-5)
// One block per (q-tile of 64 rows, head). Streams k/v tiles; S never hits
// global memory.
// smem: qs/ks/vs 64x129, s2 64x65, z 64  -> 115968 bytes dynamic
// ---------------------------------------------------------------------------
__global__ __launch_bounds__(256) void rebased_attn() {
    extern __shared__ float sm[];
    float* qs  = sm;                     // 64*129
    float* ks  = qs + 64 * 129;          // 64*129
    float* vs  = ks + 64 * 129;          // 64*129
    float* s2  = vs + 64 * 129;          // 64*65
    float* zsh = s2 + 64 * 65;           // 64

    const int tid = threadIdx.x;
    const int tx = tid & 15;
    const int ty = tid >> 4;
    const int qt = blockIdx.x;           // 0..31
    const int h  = blockIdx.y;           // 0..15
    const int q0 = qt * 64;

    // load q tile (64 x 128)
#pragma unroll
    for (int it = 0; it < 8; it++) {
        int u   = tid + it * 256;
        int row = u >> 5;
        int c4  = (u & 31) * 4;
        float4 v4 = *(const float4*)(g_q + (size_t)(q0 + row) * CH + h * HD + c4);
        qs[row * 129 + c4 + 0] = v4.x;
        qs[row * 129 + c4 + 1] = v4.y;
        qs[row * 129 + c4 + 2] = v4.z;
        qs[row * 129 + c4 + 3] = v4.w;
    }
    if (tid < 64) zsh[tid] = 0.f;

    float o[4][8];
#pragma unroll
    for (int i = 0; i < 4; i++)
#pragma unroll
        for (int c = 0; c < 8; c++) o[i][c] = 0.f;

    for (int kt = 0; kt <= qt; kt++) {
        const int k0 = kt * 64;
        __syncthreads();  // ks/vs/s2 free from previous iter; q load visible

#pragma unroll
        for (int it = 0; it < 8; it++) {
            int u   = tid + it * 256;
            int row = u >> 5;
            int c4  = (u & 31) * 4;
            float4 vk = *(const float4*)(g_k + (size_t)(k0 + row) * CH + h * HD + c4);
            ks[row * 129 + c4 + 0] = vk.x;
            ks[row * 129 + c4 + 1] = vk.y;
            ks[row * 129 + c4 + 2] = vk.z;
            ks[row * 129 + c4 + 3] = vk.w;
            float4 vv = *(const float4*)(g_v + (size_t)(k0 + row) * CH + h * HD + c4);
            vs[row * 129 + c4 + 0] = vv.x;
            vs[row * 129 + c4 + 1] = vv.y;
            vs[row * 129 + c4 + 2] = vv.z;
            vs[row * 129 + c4 + 3] = vv.w;
        }
        __syncthreads();

        // S = q . k^T  (64x64, 4x4 per thread)
        float acc[4][4];
#pragma unroll
        for (int i = 0; i < 4; i++)
#pragma unroll
            for (int j = 0; j < 4; j++) acc[i][j] = 0.f;

#pragma unroll 4
        for (int d = 0; d < 128; d++) {
            float a[4], b[4];
#pragma unroll
            for (int i = 0; i < 4; i++) a[i] = qs[(ty * 4 + i) * 129 + d];
#pragma unroll
            for (int j = 0; j < 4; j++) b[j] = ks[(tx * 4 + j) * 129 + d];
#pragma unroll
            for (int i = 0; i < 4; i++)
#pragma unroll
                for (int j = 0; j < 4; j++) acc[i][j] += a[i] * b[j];
        }

        // square, causal mask (diagonal tile only), z partial, store S^2
        const bool diag = (kt == qt);
        float zp[4] = {0.f, 0.f, 0.f, 0.f};
#pragma unroll
        for (int i = 0; i < 4; i++) {
            int li = ty * 4 + i;
#pragma unroll
            for (int j = 0; j < 4; j++) {
                int lj = tx * 4 + j;
                float sv = acc[i][j];
                sv = sv * sv;
                if (diag && lj > li) sv = 0.f;
                s2[li * 65 + lj] = sv;
                zp[i] += sv;
            }
        }
#pragma unroll
        for (int i = 0; i < 4; i++) atomicAdd(&zsh[ty * 4 + i], zp[i]);
        __syncthreads();

        // O += S^2 @ V   (64x128, 4 rows x 8 cols per thread, split cols)
        for (int j = 0; j < 64; j++) {
            float sv[4];
#pragma unroll
            for (int i = 0; i < 4; i++) sv[i] = s2[(ty * 4 + i) * 65 + j];
            float vv[8];
#pragma unroll
            for (int c = 0; c < 4; c++) {
                vv[c]     = vs[j * 129 + tx * 4 + c];
                vv[c + 4] = vs[j * 129 + 64 + tx * 4 + c];
            }
#pragma unroll
            for (int i = 0; i < 4; i++)
#pragma unroll
                for (int c = 0; c < 8; c++) o[i][c] += sv[i] * vv[c];
        }
    }
    __syncthreads();

    // divide by (z + EPS) and store
#pragma unroll
    for (int i = 0; i < 4; i++) {
        int li = ty * 4 + i;
        float inv = 1.0f / (zsh[li] + 1e-5f);
        float* op = g_o + (size_t)(q0 + li) * CH + h * HD;
#pragma unroll
        for (int c = 0; c < 4; c++) {
            op[tx * 4 + c]      = o[i][c] * inv;
            op[64 + tx * 4 + c] = o[i][c + 4] * inv;
        }
    }
}

// ---------------------------------------------------------------------------
extern "C" void kernel_launch(void* const* d_in, const int* in_sizes, int n_in,
                              void* d_out, int out_size) {
    const float* X     = (const float*)d_in[0];
    const float* Wq    = (const float*)d_in[1];
    const float* Wk    = (const float*)d_in[2];
    const float* Wv    = (const float*)d_in[3];
    const float* Wo    = (const float*)d_in[4];
    const float* gamma = (const float*)d_in[5];
    const float* beta  = (const float*)d_in[6];
    float* out = (float*)d_out;

    float *q, *k, *v, *o;
    cudaGetSymbolAddress((void**)&q, g_q);
    cudaGetSymbolAddress((void**)&k, g_k);
    cudaGetSymbolAddress((void**)&v, g_v);
    cudaGetSymbolAddress((void**)&o, g_o);

    const int ATTN_SMEM = (3 * 64 * 129 + 64 * 65 + 64) * (int)sizeof(float);
    cudaFuncSetAttribute(rebased_attn,
                         cudaFuncAttributeMaxDynamicSharedMemorySize, ATTN_SMEM);

    dim3 gGemm(16, 16), b256(256);

    // Q/K/V projections
    sgemm_tn<<<gGemm, b256>>>(X, Wq, q);
    sgemm_tn<<<gGemm, b256>>>(X, Wk, k);
    sgemm_tn<<<gGemm, b256>>>(X, Wv, v);

    // feature map (q scaled by D^-0.5, k unscaled)
    featmap<<<dim3(TSEQ * NH / 8, 2), b256>>>(gamma, beta);

    // causal quadratic attention
    rebased_attn<<<dim3(TSEQ / 64, NH), b256, ATTN_SMEM>>>();

    // output projection
    sgemm_tn<<<gGemm, b256>>>(o, Wo, out);
}

// round 5
// speedup vs baseline: 1.8203x; 1.8203x over previous
#include <cuda_runtime.h>
#include <cstdint>

#define TSEQ 2048
#define CH   2048
#define NH   16
#define HD   128

// Scratch (allocation-free rule: __device__ globals)
__device__ float g_q[TSEQ * CH];
__device__ float g_k[TSEQ * CH];
__device__ float g_v[TSEQ * CH];
__device__ float g_o[TSEQ * CH];

// ===========================================================================
// helpers
// ===========================================================================
__device__ __forceinline__ uint32_t smem_to_u32(const void* p) {
    uint32_t a;
    asm("{ .reg .u64 t; cvta.to.shared.u64 t, %1; cvt.u32.u64 %0, t; }"
        : "=r"(a) : "l"(p));
    return a;
}

__device__ __forceinline__ void cp_async16(uint32_t dst, const void* src) {
    asm volatile("cp.async.cg.shared.global [%0], [%1], 16;"
                 :: "r"(dst), "l"(src) : "memory");
}
#define CP_COMMIT() asm volatile("cp.async.commit_group;" ::: "memory")
#define CP_WAIT0()  asm volatile("cp.async.wait_group 0;" ::: "memory")

__device__ __forceinline__ uint32_t f2tf32(float x) {
    uint32_t r;
    asm("cvt.rna.tf32.f32 %0, %1;" : "=r"(r) : "f"(x));
    return r;
}

// D = A @ B + C, m16n8k8 tf32, row.col
__device__ __forceinline__ void mma_tf32(float* d, const uint32_t* a,
                                         const uint32_t* b, const float* c) {
    asm volatile(
        "mma.sync.aligned.m16n8k8.row.col.f32.tf32.tf32.f32 "
        "{%0,%1,%2,%3}, {%4,%5,%6,%7}, {%8,%9}, {%10,%11,%12,%13};"
        : "=f"(d[0]), "=f"(d[1]), "=f"(d[2]), "=f"(d[3])
        : "r"(a[0]), "r"(a[1]), "r"(a[2]), "r"(a[3]),
          "r"(b[0]), "r"(b[1]),
          "f"(c[0]), "f"(c[1]), "f"(c[2]), "f"(c[3]));
}

// ===========================================================================
// C[M,N] = A[M,K] @ B[N,K]^T   (M=N=K=2048, row-major) via tf32 mma.sync
// CTA 128x128, BK=16, 8 warps (warp tile 64x32), double-buffered cp.async.
// smem layout: As[stage][128][20], Bs[stage][128][20] (pad 4 floats ->
// conflict-free fragment gathers: bank = (20*r + k) % 32, all distinct)
// ===========================================================================
#define BK    16
#define LDS_P 20
#define NTIL  (CH / BK)   // 128

__global__ __launch_bounds__(256, 2) void mma_gemm_tn(const float* __restrict__ A,
                                                      const float* __restrict__ B,
                                                      float* __restrict__ C) {
    __shared__ float As[2][128][LDS_P];
    __shared__ float Bs[2][128][LDS_P];

    const int tid  = threadIdx.x;
    const int lane = tid & 31;
    const int wid  = tid >> 5;
    const int wm   = (wid & 1) * 64;    // warp m-offset within CTA tile
    const int wn   = (wid >> 1) * 32;   // warp n-offset

    const int m0 = blockIdx.y * 128;
    const int n0 = blockIdx.x * 128;
    const float* Ab = A + (size_t)m0 * CH;
    const float* Bb = B + (size_t)n0 * CH;

    const uint32_t sA0 = smem_to_u32(&As[0][0][0]);
    const uint32_t sB0 = smem_to_u32(&Bs[0][0][0]);

    // load mapping: 512 16B chunks per matrix per stage, 2 per thread
    const int r0c = tid >> 2;              // chunk row for i=0 (0..63)
    const int c4  = (tid & 3) << 2;        // float offset within k-row

    float acc[4][4][4];
#pragma unroll
    for (int mt = 0; mt < 4; mt++)
#pragma unroll
        for (int nt = 0; nt < 4; nt++)
#pragma unroll
            for (int e = 0; e < 4; e++) acc[mt][nt][e] = 0.f;

    // prologue: stage 0
#pragma unroll
    for (int i = 0; i < 2; i++) {
        int row = r0c + i * 64;
        uint32_t off = (uint32_t)(row * LDS_P + c4) * 4u;
        cp_async16(sA0 + off, Ab + (size_t)row * CH + c4);
        cp_async16(sB0 + off, Bb + (size_t)row * CH + c4);
    }
    CP_COMMIT();

    for (int kt = 0; kt < NTIL; kt++) {
        CP_WAIT0();
        __syncthreads();

        if (kt + 1 < NTIL) {
            const int buf = (kt + 1) & 1;
            const int kc  = (kt + 1) * BK;
            const uint32_t sAd = sA0 + (uint32_t)(buf * 128 * LDS_P * 4);
            const uint32_t sBd = sB0 + (uint32_t)(buf * 128 * LDS_P * 4);
#pragma unroll
            for (int i = 0; i < 2; i++) {
                int row = r0c + i * 64;
                uint32_t off = (uint32_t)(row * LDS_P + c4) * 4u;
                cp_async16(sAd + off, Ab + (size_t)row * CH + kc + c4);
                cp_async16(sBd + off, Bb + (size_t)row * CH + kc + c4);
            }
            CP_COMMIT();
        }

        const int buf = kt & 1;
#pragma unroll
        for (int ks = 0; ks < 2; ks++) {
            const int k8 = ks * 8;
            uint32_t af[4][4], bf[4][2];
            const int kq = k8 + (lane & 3);
#pragma unroll
            for (int mt = 0; mt < 4; mt++) {
                int r = wm + mt * 16 + (lane >> 2);
                af[mt][0] = f2tf32(As[buf][r][kq]);
                af[mt][1] = f2tf32(As[buf][r + 8][kq]);
                af[mt][2] = f2tf32(As[buf][r][kq + 4]);
                af[mt][3] = f2tf32(As[buf][r + 8][kq + 4]);
            }
#pragma unroll
            for (int nt = 0; nt < 4; nt++) {
                int cidx = wn + nt * 8 + (lane >> 2);
                bf[nt][0] = f2tf32(Bs[buf][cidx][kq]);
                bf[nt][1] = f2tf32(Bs[buf][cidx][kq + 4]);
            }
#pragma unroll
            for (int mt = 0; mt < 4; mt++)
#pragma unroll
                for (int nt = 0; nt < 4; nt++)
                    mma_tf32(acc[mt][nt], af[mt], bf[nt], acc[mt][nt]);
        }
        __syncthreads();
    }

    // epilogue: float2 stores
#pragma unroll
    for (int mt = 0; mt < 4; mt++) {
        int r = m0 + wm + mt * 16 + (lane >> 2);
#pragma unroll
        for (int nt = 0; nt < 4; nt++) {
            int cidx = n0 + wn + nt * 8 + 2 * (lane & 3);
            *(float2*)(C + (size_t)r * CH + cidx) =
                make_float2(acc[mt][nt][0], acc[mt][nt][1]);
            *(float2*)(C + (size_t)(r + 8) * CH + cidx) =
                make_float2(acc[mt][nt][2], acc[mt][nt][3]);
        }
    }
}

// ---------------------------------------------------------------------------
// ReBased feature map: y = LayerNorm(x * gamma + beta) over D=128 per (t,h)
// row, with optional D^-0.5 scale (for q). One warp per row.
// blockIdx.y == 0 -> g_q (scaled), == 1 -> g_k
// ---------------------------------------------------------------------------
__global__ __launch_bounds__(256) void featmap(const float* __restrict__ gamma,
                                               const float* __restrict__ beta) {
    const int warp = threadIdx.x >> 5;
    const int lane = threadIdx.x & 31;
    const int row  = blockIdx.x * 8 + warp;   // 0 .. T*NH-1
    float* base = (blockIdx.y == 0) ? g_q : g_k;
    const float scale = (blockIdx.y == 0) ? 0.08838834764831845f : 1.0f;  // D^-0.5
    const int t = row >> 4;
    const int h = row & 15;
    float* p = base + (size_t)t * CH + h * HD;

    float x[4];
    float s = 0.f, sq = 0.f;
#pragma unroll
    for (int r = 0; r < 4; r++) {
        int d = lane + 32 * r;
        float y = p[d] * gamma[d] + beta[d];
        x[r] = y;
        s  += y;
        sq += y * y;
    }
#pragma unroll
    for (int o = 16; o; o >>= 1) {
        s  += __shfl_xor_sync(0xFFFFFFFFu, s, o);
        sq += __shfl_xor_sync(0xFFFFFFFFu, sq, o);
    }
    const float mu  = s * (1.0f / HD);
    const float var = sq * (1.0f / HD) - mu * mu;
    const float rs  = rsqrtf(var + 1e-5f) * scale;
#pragma unroll
    for (int r = 0; r < 4; r++) p[lane + 32 * r] = (x[r] - mu) * rs;
}

// ---------------------------------------------------------------------------
// Causal quadratic attention (no softmax):
//   S = (q . k)^2 (causal), O = S @ v, z = rowsum(S), out = O / (z + 1e-5)
// One block per (q-tile of 64 rows, head). Streams k/v tiles; S never hits
// global memory.
// ---------------------------------------------------------------------------
__global__ __launch_bounds__(256) void rebased_attn() {
    extern __shared__ float smx[];
    float* qs  = smx;                    // 64*129
    float* ks  = qs + 64 * 129;          // 64*129
    float* vs  = ks + 64 * 129;          // 64*129
    float* s2  = vs + 64 * 129;          // 64*65
    float* zsh = s2 + 64 * 65;           // 64

    const int tid = threadIdx.x;
    const int tx = tid & 15;
    const int ty = tid >> 4;
    const int qt = blockIdx.x;           // 0..31
    const int h  = blockIdx.y;           // 0..15
    const int q0 = qt * 64;

#pragma unroll
    for (int it = 0; it < 8; it++) {
        int u   = tid + it * 256;
        int row = u >> 5;
        int c4  = (u & 31) * 4;
        float4 v4 = *(const float4*)(g_q + (size_t)(q0 + row) * CH + h * HD + c4);
        qs[row * 129 + c4 + 0] = v4.x;
        qs[row * 129 + c4 + 1] = v4.y;
        qs[row * 129 + c4 + 2] = v4.z;
        qs[row * 129 + c4 + 3] = v4.w;
    }
    if (tid < 64) zsh[tid] = 0.f;

    float o[4][8];
#pragma unroll
    for (int i = 0; i < 4; i++)
#pragma unroll
        for (int c = 0; c < 8; c++) o[i][c] = 0.f;

    for (int kt = 0; kt <= qt; kt++) {
        const int k0 = kt * 64;
        __syncthreads();

#pragma unroll
        for (int it = 0; it < 8; it++) {
            int u   = tid + it * 256;
            int row = u >> 5;
            int c4  = (u & 31) * 4;
            float4 vk = *(const float4*)(g_k + (size_t)(k0 + row) * CH + h * HD + c4);
            ks[row * 129 + c4 + 0] = vk.x;
            ks[row * 129 + c4 + 1] = vk.y;
            ks[row * 129 + c4 + 2] = vk.z;
            ks[row * 129 + c4 + 3] = vk.w;
            float4 vv = *(const float4*)(g_v + (size_t)(k0 + row) * CH + h * HD + c4);
            vs[row * 129 + c4 + 0] = vv.x;
            vs[row * 129 + c4 + 1] = vv.y;
            vs[row * 129 + c4 + 2] = vv.z;
            vs[row * 129 + c4 + 3] = vv.w;
        }
        __syncthreads();

        float acc[4][4];
#pragma unroll
        for (int i = 0; i < 4; i++)
#pragma unroll
            for (int j = 0; j < 4; j++) acc[i][j] = 0.f;

#pragma unroll 4
        for (int d = 0; d < 128; d++) {
            float a[4], b[4];
#pragma unroll
            for (int i = 0; i < 4; i++) a[i] = qs[(ty * 4 + i) * 129 + d];
#pragma unroll
            for (int j = 0; j < 4; j++) b[j] = ks[(tx * 4 + j) * 129 + d];
#pragma unroll
            for (int i = 0; i < 4; i++)
#pragma unroll
                for (int j = 0; j < 4; j++) acc[i][j] += a[i] * b[j];
        }

        const bool diag = (kt == qt);
        float zp[4] = {0.f, 0.f, 0.f, 0.f};
#pragma unroll
        for (int i = 0; i < 4; i++) {
            int li = ty * 4 + i;
#pragma unroll
            for (int j = 0; j < 4; j++) {
                int lj = tx * 4 + j;
                float sv = acc[i][j];
                sv = sv * sv;
                if (diag && lj > li) sv = 0.f;
                s2[li * 65 + lj] = sv;
                zp[i] += sv;
            }
        }
#pragma unroll
        for (int i = 0; i < 4; i++) atomicAdd(&zsh[ty * 4 + i], zp[i]);
        __syncthreads();

        for (int j = 0; j < 64; j++) {
            float sv[4];
#pragma unroll
            for (int i = 0; i < 4; i++) sv[i] = s2[(ty * 4 + i) * 65 + j];
            float vv[8];
#pragma unroll
            for (int c = 0; c < 4; c++) {
                vv[c]     = vs[j * 129 + tx * 4 + c];
                vv[c + 4] = vs[j * 129 + 64 + tx * 4 + c];
            }
#pragma unroll
            for (int i = 0; i < 4; i++)
#pragma unroll
                for (int c = 0; c < 8; c++) o[i][c] += sv[i] * vv[c];
        }
    }
    __syncthreads();

#pragma unroll
    for (int i = 0; i < 4; i++) {
        int li = ty * 4 + i;
        float inv = 1.0f / (zsh[li] + 1e-5f);
        float* op = g_o + (size_t)(q0 + li) * CH + h * HD;
#pragma unroll
        for (int c = 0; c < 4; c++) {
            op[tx * 4 + c]      = o[i][c] * inv;
            op[64 + tx * 4 + c] = o[i][c + 4] * inv;
        }
    }
}

// ---------------------------------------------------------------------------
extern "C" void kernel_launch(void* const* d_in, const int* in_sizes, int n_in,
                              void* d_out, int out_size) {
    const float* X     = (const float*)d_in[0];
    const float* Wq    = (const float*)d_in[1];
    const float* Wk    = (const float*)d_in[2];
    const float* Wv    = (const float*)d_in[3];
    const float* Wo    = (const float*)d_in[4];
    const float* gamma = (const float*)d_in[5];
    const float* beta  = (const float*)d_in[6];
    float* out = (float*)d_out;

    float *q, *k, *v, *o;
    cudaGetSymbolAddress((void**)&q, g_q);
    cudaGetSymbolAddress((void**)&k, g_k);
    cudaGetSymbolAddress((void**)&v, g_v);
    cudaGetSymbolAddress((void**)&o, g_o);

    const int ATTN_SMEM = (3 * 64 * 129 + 64 * 65 + 64) * (int)sizeof(float);
    cudaFuncSetAttribute(rebased_attn,
                         cudaFuncAttributeMaxDynamicSharedMemorySize, ATTN_SMEM);

    dim3 gGemm(16, 16), b256(256);

    // Q/K/V projections (tf32 mma.sync)
    mma_gemm_tn<<<gGemm, b256>>>(X, Wq, q);
    mma_gemm_tn<<<gGemm, b256>>>(X, Wk, k);
    mma_gemm_tn<<<gGemm, b256>>>(X, Wv, v);

    // feature map (q scaled by D^-0.5, k unscaled)
    featmap<<<dim3(TSEQ * NH / 8, 2), b256>>>(gamma, beta);

    // causal quadratic attention
    rebased_attn<<<dim3(TSEQ / 64, NH), b256, ATTN_SMEM>>>();

    // output projection (tf32 mma.sync)
    mma_gemm_tn<<<gGemm, b256>>>(o, Wo, out);
}

// round 6
// speedup vs baseline: 2.5538x; 1.4030x over previous
#include <cuda_runtime.h>
#include <cstdint>

#define TSEQ 2048
#define CH   2048
#define NH   16
#define HD   128

// Scratch (allocation-free rule: __device__ globals)
__device__ float g_q[TSEQ * CH];
__device__ float g_k[TSEQ * CH];
__device__ float g_v[TSEQ * CH];
__device__ float g_o[TSEQ * CH];

// ===========================================================================
// helpers
// ===========================================================================
__device__ __forceinline__ uint32_t smem_to_u32(const void* p) {
    uint32_t a;
    asm("{ .reg .u64 t; cvta.to.shared.u64 t, %1; cvt.u32.u64 %0, t; }"
        : "=r"(a) : "l"(p));
    return a;
}

__device__ __forceinline__ void cp_async16(uint32_t dst, const void* src) {
    asm volatile("cp.async.cg.shared.global [%0], [%1], 16;"
                 :: "r"(dst), "l"(src) : "memory");
}
#define CP_COMMIT() asm volatile("cp.async.commit_group;" ::: "memory")
#define CP_WAIT0()  asm volatile("cp.async.wait_group 0;" ::: "memory")

__device__ __forceinline__ uint32_t f2tf32(float x) {
    uint32_t r;
    asm("cvt.rna.tf32.f32 %0, %1;" : "=r"(r) : "f"(x));
    return r;
}
__device__ __forceinline__ float tf32r(float x) {
    return __uint_as_float(f2tf32(x));
}

// D = A @ B + C, m16n8k8 tf32, row.col
__device__ __forceinline__ void mma_tf32(float* d, const uint32_t* a,
                                         const uint32_t* b, const float* c) {
    asm volatile(
        "mma.sync.aligned.m16n8k8.row.col.f32.tf32.tf32.f32 "
        "{%0,%1,%2,%3}, {%4,%5,%6,%7}, {%8,%9}, {%10,%11,%12,%13};"
        : "=f"(d[0]), "=f"(d[1]), "=f"(d[2]), "=f"(d[3])
        : "r"(a[0]), "r"(a[1]), "r"(a[2]), "r"(a[3]),
          "r"(b[0]), "r"(b[1]),
          "f"(c[0]), "f"(c[1]), "f"(c[2]), "f"(c[3]));
}

// ===========================================================================
// C[M,N] = A[M,K] @ B[N,K]^T   (M=N=K=2048, row-major) via tf32 mma.sync
// (verified in R5)
// ===========================================================================
#define BK    16
#define LDS_P 20
#define NTIL  (CH / BK)   // 128

__global__ __launch_bounds__(256, 2) void mma_gemm_tn(const float* __restrict__ A,
                                                      const float* __restrict__ B,
                                                      float* __restrict__ C) {
    __shared__ float As[2][128][LDS_P];
    __shared__ float Bs[2][128][LDS_P];

    const int tid  = threadIdx.x;
    const int lane = tid & 31;
    const int wid  = tid >> 5;
    const int wm   = (wid & 1) * 64;
    const int wn   = (wid >> 1) * 32;

    const int m0 = blockIdx.y * 128;
    const int n0 = blockIdx.x * 128;
    const float* Ab = A + (size_t)m0 * CH;
    const float* Bb = B + (size_t)n0 * CH;

    const uint32_t sA0 = smem_to_u32(&As[0][0][0]);
    const uint32_t sB0 = smem_to_u32(&Bs[0][0][0]);

    const int r0c = tid >> 2;
    const int c4  = (tid & 3) << 2;

    float acc[4][4][4];
#pragma unroll
    for (int mt = 0; mt < 4; mt++)
#pragma unroll
        for (int nt = 0; nt < 4; nt++)
#pragma unroll
            for (int e = 0; e < 4; e++) acc[mt][nt][e] = 0.f;

#pragma unroll
    for (int i = 0; i < 2; i++) {
        int row = r0c + i * 64;
        uint32_t off = (uint32_t)(row * LDS_P + c4) * 4u;
        cp_async16(sA0 + off, Ab + (size_t)row * CH + c4);
        cp_async16(sB0 + off, Bb + (size_t)row * CH + c4);
    }
    CP_COMMIT();

    for (int kt = 0; kt < NTIL; kt++) {
        CP_WAIT0();
        __syncthreads();

        if (kt + 1 < NTIL) {
            const int buf = (kt + 1) & 1;
            const int kc  = (kt + 1) * BK;
            const uint32_t sAd = sA0 + (uint32_t)(buf * 128 * LDS_P * 4);
            const uint32_t sBd = sB0 + (uint32_t)(buf * 128 * LDS_P * 4);
#pragma unroll
            for (int i = 0; i < 2; i++) {
                int row = r0c + i * 64;
                uint32_t off = (uint32_t)(row * LDS_P + c4) * 4u;
                cp_async16(sAd + off, Ab + (size_t)row * CH + kc + c4);
                cp_async16(sBd + off, Bb + (size_t)row * CH + kc + c4);
            }
            CP_COMMIT();
        }

        const int buf = kt & 1;
#pragma unroll
        for (int ks = 0; ks < 2; ks++) {
            const int k8 = ks * 8;
            uint32_t af[4][4], bf[4][2];
            const int kq = k8 + (lane & 3);
#pragma unroll
            for (int mt = 0; mt < 4; mt++) {
                int r = wm + mt * 16 + (lane >> 2);
                af[mt][0] = f2tf32(As[buf][r][kq]);
                af[mt][1] = f2tf32(As[buf][r + 8][kq]);
                af[mt][2] = f2tf32(As[buf][r][kq + 4]);
                af[mt][3] = f2tf32(As[buf][r + 8][kq + 4]);
            }
#pragma unroll
            for (int nt = 0; nt < 4; nt++) {
                int cidx = wn + nt * 8 + (lane >> 2);
                bf[nt][0] = f2tf32(Bs[buf][cidx][kq]);
                bf[nt][1] = f2tf32(Bs[buf][cidx][kq + 4]);
            }
#pragma unroll
            for (int mt = 0; mt < 4; mt++)
#pragma unroll
                for (int nt = 0; nt < 4; nt++)
                    mma_tf32(acc[mt][nt], af[mt], bf[nt], acc[mt][nt]);
        }
        __syncthreads();
    }

#pragma unroll
    for (int mt = 0; mt < 4; mt++) {
        int r = m0 + wm + mt * 16 + (lane >> 2);
#pragma unroll
        for (int nt = 0; nt < 4; nt++) {
            int cidx = n0 + wn + nt * 8 + 2 * (lane & 3);
            *(float2*)(C + (size_t)r * CH + cidx) =
                make_float2(acc[mt][nt][0], acc[mt][nt][1]);
            *(float2*)(C + (size_t)(r + 8) * CH + cidx) =
                make_float2(acc[mt][nt][2], acc[mt][nt][3]);
        }
    }
}

// ---------------------------------------------------------------------------
// ReBased feature map (unchanged)
// ---------------------------------------------------------------------------
__global__ __launch_bounds__(256) void featmap(const float* __restrict__ gamma,
                                               const float* __restrict__ beta) {
    const int warp = threadIdx.x >> 5;
    const int lane = threadIdx.x & 31;
    const int row  = blockIdx.x * 8 + warp;
    float* base = (blockIdx.y == 0) ? g_q : g_k;
    const float scale = (blockIdx.y == 0) ? 0.08838834764831845f : 1.0f;
    const int t = row >> 4;
    const int h = row & 15;
    float* p = base + (size_t)t * CH + h * HD;

    float x[4];
    float s = 0.f, sq = 0.f;
#pragma unroll
    for (int r = 0; r < 4; r++) {
        int d = lane + 32 * r;
        float y = p[d] * gamma[d] + beta[d];
        x[r] = y;
        s  += y;
        sq += y * y;
    }
#pragma unroll
    for (int o = 16; o; o >>= 1) {
        s  += __shfl_xor_sync(0xFFFFFFFFu, s, o);
        sq += __shfl_xor_sync(0xFFFFFFFFu, sq, o);
    }
    const float mu  = s * (1.0f / HD);
    const float var = sq * (1.0f / HD) - mu * mu;
    const float rs  = rsqrtf(var + 1e-5f) * scale;
#pragma unroll
    for (int r = 0; r < 4; r++) p[lane + 32 * r] = (x[r] - mu) * rs;
}

// ===========================================================================
// Causal quadratic attention via tf32 mma.sync:
//   S = q.k^T with 3-pass split-tf32 (hi*hi + hi*lo + lo*hi)  -> ~fp32 exact
//   S2 = masked S^2 (fp32 regs), z += rowsum(S2) (fp32 atomics)
//   O += S2 @ V with 1-pass tf32 (v pre-rounded, stored transposed)
// One CTA per (q-tile of 64 rows, head), 8 warps.
// smem: q_hl[64][132] f2 | k_hl[64][132] f2 | vt[128][68] f | s2[64][68] f | z[64]
// ===========================================================================
#define WQK 132   // float2 pitch for q_hl/k_hl (8r+2k bank pattern, phase-clean)
#define WVT 68    // float pitch for vt/s2 (4r+k pattern, conflict-free)
#define ATTN_SMEM2 (2 * 64 * WQK * 8 + 128 * WVT * 4 + 64 * WVT * 4 + 64 * 4)

__global__ __launch_bounds__(256, 1) void rebased_attn_mma() {
    extern __shared__ __align__(16) char dynsm[];
    float2* q_hl = (float2*)dynsm;                 // [64][WQK]
    float2* k_hl = q_hl + 64 * WQK;                // [64][WQK]
    float*  vt   = (float*)(k_hl + 64 * WQK);      // [128][WVT]
    float*  s2m  = vt + 128 * WVT;                 // [64][WVT]
    float*  zsh  = s2m + 64 * WVT;                 // [64]

    const int tid  = threadIdx.x;
    const int lane = tid & 31;
    const int wid  = tid >> 5;
    const int qt   = 31 - blockIdx.x;   // heavy tiles first
    const int h    = blockIdx.y;
    const int q0   = qt * 64;

    const int wmQ = (wid & 1) * 32, wnQ = (wid >> 1) * 16;  // QK warp tile 32x16
    const int wmO = (wid & 1) * 32, wnO = (wid >> 1) * 32;  // SV warp tile 32x32

    // ---- load q tile, split hi/lo ----
    {
        const int row = tid >> 2;
        const int cb  = (tid & 3) * 4;
        const float* src = g_q + (size_t)(q0 + row) * CH + h * HD;
        float2* dst = q_hl + row * WQK;
#pragma unroll
        for (int c = 0; c < 8; c++) {
            float4 x = *(const float4*)(src + c * 16 + cb);
            float xs[4] = {x.x, x.y, x.z, x.w};
#pragma unroll
            for (int i = 0; i < 4; i++) {
                float hi = tf32r(xs[i]);
                float lo = tf32r(xs[i] - hi);
                dst[c * 16 + cb + i] = make_float2(hi, lo);
            }
        }
    }
    if (tid < 64) zsh[tid] = 0.f;

    float oacc[2][4][4];
#pragma unroll
    for (int mt = 0; mt < 2; mt++)
#pragma unroll
        for (int nt = 0; nt < 4; nt++)
#pragma unroll
            for (int e = 0; e < 4; e++) oacc[mt][nt][e] = 0.f;

    for (int kt = 0; kt <= qt; kt++) {
        const int k0 = kt * 64;
        __syncthreads();   // prev iter's k_hl/vt/s2m fully consumed

        // ---- load k tile, split hi/lo ----
        {
            const int row = tid >> 2;
            const int cb  = (tid & 3) * 4;
            const float* src = g_k + (size_t)(k0 + row) * CH + h * HD;
            float2* dst = k_hl + row * WQK;
#pragma unroll
            for (int c = 0; c < 8; c++) {
                float4 x = *(const float4*)(src + c * 16 + cb);
                float xs[4] = {x.x, x.y, x.z, x.w};
#pragma unroll
                for (int i = 0; i < 4; i++) {
                    float hi = tf32r(xs[i]);
                    float lo = tf32r(xs[i] - hi);
                    dst[c * 16 + cb + i] = make_float2(hi, lo);
                }
            }
        }
        // ---- load v tile transposed (vt[d][j]), tf32 pre-rounded ----
        {
            const int jv = tid & 63;
            const int db = (tid >> 6) * 4;
            const float* src = g_v + (size_t)(k0 + jv) * CH + h * HD;
#pragma unroll
            for (int c = 0; c < 8; c++) {
                int d0 = db + c * 16;
                float4 x = *(const float4*)(src + d0);
                vt[(d0 + 0) * WVT + jv] = tf32r(x.x);
                vt[(d0 + 1) * WVT + jv] = tf32r(x.y);
                vt[(d0 + 2) * WVT + jv] = tf32r(x.z);
                vt[(d0 + 3) * WVT + jv] = tf32r(x.w);
            }
        }
        __syncthreads();

        // ---- S = q.k^T, 3-pass split tf32 ----
        float sacc[2][2][4];
#pragma unroll
        for (int mt = 0; mt < 2; mt++)
#pragma unroll
            for (int nt = 0; nt < 2; nt++)
#pragma unroll
                for (int e = 0; e < 4; e++) sacc[mt][nt][e] = 0.f;

#pragma unroll 4
        for (int k8 = 0; k8 < 16; k8++) {
            const int kq = k8 * 8 + (lane & 3);
            float2 a[2][4], b[2][2];
#pragma unroll
            for (int mt = 0; mt < 2; mt++) {
                int r = wmQ + mt * 16 + (lane >> 2);
                a[mt][0] = q_hl[r * WQK + kq];
                a[mt][1] = q_hl[(r + 8) * WQK + kq];
                a[mt][2] = q_hl[r * WQK + kq + 4];
                a[mt][3] = q_hl[(r + 8) * WQK + kq + 4];
            }
#pragma unroll
            for (int nt = 0; nt < 2; nt++) {
                int n = wnQ + nt * 8 + (lane >> 2);
                b[nt][0] = k_hl[n * WQK + kq];
                b[nt][1] = k_hl[n * WQK + kq + 4];
            }
#pragma unroll
            for (int mt = 0; mt < 2; mt++) {
                uint32_t ah[4] = {__float_as_uint(a[mt][0].x), __float_as_uint(a[mt][1].x),
                                  __float_as_uint(a[mt][2].x), __float_as_uint(a[mt][3].x)};
                uint32_t al[4] = {__float_as_uint(a[mt][0].y), __float_as_uint(a[mt][1].y),
                                  __float_as_uint(a[mt][2].y), __float_as_uint(a[mt][3].y)};
#pragma unroll
                for (int nt = 0; nt < 2; nt++) {
                    uint32_t bh[2] = {__float_as_uint(b[nt][0].x), __float_as_uint(b[nt][1].x)};
                    uint32_t bl[2] = {__float_as_uint(b[nt][0].y), __float_as_uint(b[nt][1].y)};
                    mma_tf32(sacc[mt][nt], ah, bh, sacc[mt][nt]);
                    mma_tf32(sacc[mt][nt], ah, bl, sacc[mt][nt]);
                    mma_tf32(sacc[mt][nt], al, bh, sacc[mt][nt]);
                }
            }
        }

        // ---- square, mask, store s2, accumulate z ----
        const bool diag = (kt == qt);
#pragma unroll
        for (int mt = 0; mt < 2; mt++) {
            const int r0l = wmQ + mt * 16 + (lane >> 2);
            float zp0 = 0.f, zp1 = 0.f;
#pragma unroll
            for (int nt = 0; nt < 2; nt++) {
                const int c0l = wnQ + nt * 8 + 2 * (lane & 3);
                float s0 = sacc[mt][nt][0]; s0 *= s0;
                float s1 = sacc[mt][nt][1]; s1 *= s1;
                float s2 = sacc[mt][nt][2]; s2 *= s2;
                float s3 = sacc[mt][nt][3]; s3 *= s3;
                if (diag) {
                    if (c0l > r0l)         s0 = 0.f;
                    if (c0l + 1 > r0l)     s1 = 0.f;
                    if (c0l > r0l + 8)     s2 = 0.f;
                    if (c0l + 1 > r0l + 8) s3 = 0.f;
                }
                *(float2*)&s2m[r0l * WVT + c0l]       = make_float2(s0, s1);
                *(float2*)&s2m[(r0l + 8) * WVT + c0l] = make_float2(s2, s3);
                zp0 += s0 + s1;
                zp1 += s2 + s3;
            }
            atomicAdd(&zsh[r0l], zp0);
            atomicAdd(&zsh[r0l + 8], zp1);
        }
        __syncthreads();

        // ---- O += S2 @ V (1-pass tf32) ----
#pragma unroll 2
        for (int k8 = 0; k8 < 8; k8++) {
            const int kq = k8 * 8 + (lane & 3);
            uint32_t a[2][4];
#pragma unroll
            for (int mt = 0; mt < 2; mt++) {
                int r = wmO + mt * 16 + (lane >> 2);
                a[mt][0] = f2tf32(s2m[r * WVT + kq]);
                a[mt][1] = f2tf32(s2m[(r + 8) * WVT + kq]);
                a[mt][2] = f2tf32(s2m[r * WVT + kq + 4]);
                a[mt][3] = f2tf32(s2m[(r + 8) * WVT + kq + 4]);
            }
            uint32_t b[4][2];
#pragma unroll
            for (int nt = 0; nt < 4; nt++) {
                int n = wnO + nt * 8 + (lane >> 2);
                b[nt][0] = __float_as_uint(vt[n * WVT + kq]);
                b[nt][1] = __float_as_uint(vt[n * WVT + kq + 4]);
            }
#pragma unroll
            for (int mt = 0; mt < 2; mt++)
#pragma unroll
                for (int nt = 0; nt < 4; nt++)
                    mma_tf32(oacc[mt][nt], a[mt], b[nt], oacc[mt][nt]);
        }
    }
    __syncthreads();   // final z atomics visible

    // ---- epilogue: divide by (z + eps), store ----
#pragma unroll
    for (int mt = 0; mt < 2; mt++) {
        const int rl = wmO + mt * 16 + (lane >> 2);
        const float inv0 = 1.0f / (zsh[rl] + 1e-5f);
        const float inv1 = 1.0f / (zsh[rl + 8] + 1e-5f);
        float* o0 = g_o + (size_t)(q0 + rl) * CH + h * HD;
        float* o1 = g_o + (size_t)(q0 + rl + 8) * CH + h * HD;
#pragma unroll
        for (int nt = 0; nt < 4; nt++) {
            const int cl = wnO + nt * 8 + 2 * (lane & 3);
            *(float2*)(o0 + cl) = make_float2(oacc[mt][nt][0] * inv0,
                                              oacc[mt][nt][1] * inv0);
            *(float2*)(o1 + cl) = make_float2(oacc[mt][nt][2] * inv1,
                                              oacc[mt][nt][3] * inv1);
        }
    }
}

// ---------------------------------------------------------------------------
extern "C" void kernel_launch(void* const* d_in, const int* in_sizes, int n_in,
                              void* d_out, int out_size) {
    const float* X     = (const float*)d_in[0];
    const float* Wq    = (const float*)d_in[1];
    const float* Wk    = (const float*)d_in[2];
    const float* Wv    = (const float*)d_in[3];
    const float* Wo    = (const float*)d_in[4];
    const float* gamma = (const float*)d_in[5];
    const float* beta  = (const float*)d_in[6];
    float* out = (float*)d_out;

    float *q, *k, *v, *o;
    cudaGetSymbolAddress((void**)&q, g_q);
    cudaGetSymbolAddress((void**)&k, g_k);
    cudaGetSymbolAddress((void**)&v, g_v);
    cudaGetSymbolAddress((void**)&o, g_o);

    cudaFuncSetAttribute(rebased_attn_mma,
                         cudaFuncAttributeMaxDynamicSharedMemorySize, ATTN_SMEM2);

    dim3 gGemm(16, 16), b256(256);

    // Q/K/V projections (tf32 mma.sync)
    mma_gemm_tn<<<gGemm, b256>>>(X, Wq, q);
    mma_gemm_tn<<<gGemm, b256>>>(X, Wk, k);
    mma_gemm_tn<<<gGemm, b256>>>(X, Wv, v);

    // feature map (q scaled by D^-0.5, k unscaled)
    featmap<<<dim3(TSEQ * NH / 8, 2), b256>>>(gamma, beta);

    // causal quadratic attention (tf32 mma, split-tf32 scores)
    rebased_attn_mma<<<dim3(TSEQ / 64, NH), b256, ATTN_SMEM2>>>();

    // output projection (tf32 mma.sync)
    mma_gemm_tn<<<gGemm, b256>>>(o, Wo, out);
}

// round 7
// speedup vs baseline: 2.8655x; 1.1220x over previous
#include <cuda_runtime.h>
#include <cstdint>

#define TSEQ 2048
#define CH   2048
#define NH   16
#define HD   128

// Scratch (allocation-free rule: __device__ globals)
__device__ float g_q[TSEQ * CH];
__device__ float g_k[TSEQ * CH];
__device__ float g_v[TSEQ * CH];
__device__ float g_o[TSEQ * CH];
// tf32-rounded, K-group-permuted operands
__device__ float g_xp[TSEQ * CH];
__device__ float g_wqp[CH * CH];
__device__ float g_wkp[CH * CH];
__device__ float g_wvp[CH * CH];
__device__ float g_wop[CH * CH];
__device__ float g_op[TSEQ * CH];

// ===========================================================================
// helpers
// ===========================================================================
__device__ __forceinline__ uint32_t smem_to_u32(const void* p) {
    uint32_t a;
    asm("{ .reg .u64 t; cvta.to.shared.u64 t, %1; cvt.u32.u64 %0, t; }"
        : "=r"(a) : "l"(p));
    return a;
}

__device__ __forceinline__ void cp_async16(uint32_t dst, const void* src) {
    asm volatile("cp.async.cg.shared.global [%0], [%1], 16;"
                 :: "r"(dst), "l"(src) : "memory");
}
#define CP_COMMIT() asm volatile("cp.async.commit_group;" ::: "memory")
#define CP_WAIT0()  asm volatile("cp.async.wait_group 0;" ::: "memory")

__device__ __forceinline__ uint32_t f2tf32(float x) {
    uint32_t r;
    asm("cvt.rna.tf32.f32 %0, %1;" : "=r"(r) : "f"(x));
    return r;
}
__device__ __forceinline__ float tf32r(float x) {
    return __uint_as_float(f2tf32(x));
}

// D = A @ B + C, m16n8k8 tf32, row.col
__device__ __forceinline__ void mma_tf32(float* d, const uint32_t* a,
                                         const uint32_t* b, const float* c) {
    asm volatile(
        "mma.sync.aligned.m16n8k8.row.col.f32.tf32.tf32.f32 "
        "{%0,%1,%2,%3}, {%4,%5,%6,%7}, {%8,%9}, {%10,%11,%12,%13};"
        : "=f"(d[0]), "=f"(d[1]), "=f"(d[2]), "=f"(d[3])
        : "r"(a[0]), "r"(a[1]), "r"(a[2]), "r"(a[3]),
          "r"(b[0]), "r"(b[1]),
          "f"(c[0]), "f"(c[1]), "f"(c[2]), "f"(c[3]));
}

// ===========================================================================
// round-to-tf32 + permute each 8-col K-group to [0,4,1,5,2,6,3,7]
// (so (k, k+4) fragment pairs are adjacent -> LDS.64, no cvt in GEMM)
// one thread per 8-float group; blockIdx.y selects matrix
// ===========================================================================
__global__ __launch_bounds__(256) void round_permute5(
    const float* __restrict__ s0, const float* __restrict__ s1,
    const float* __restrict__ s2, const float* __restrict__ s3,
    const float* __restrict__ s4,
    float* __restrict__ d0, float* __restrict__ d1, float* __restrict__ d2,
    float* __restrict__ d3, float* __restrict__ d4, int nmat) {
    const int i = blockIdx.x * blockDim.x + threadIdx.x;   // group index
    const int m = blockIdx.y;
    if (m >= nmat) return;
    const float* s = (m == 0) ? s0 : (m == 1) ? s1 : (m == 2) ? s2
                   : (m == 3) ? s3 : s4;
    float* d = (m == 0) ? d0 : (m == 1) ? d1 : (m == 2) ? d2
             : (m == 3) ? d3 : d4;
    float4 a = *(const float4*)(s + (size_t)i * 8);
    float4 b = *(const float4*)(s + (size_t)i * 8 + 4);
    float4 o0 = make_float4(tf32r(a.x), tf32r(b.x), tf32r(a.y), tf32r(b.y));
    float4 o1 = make_float4(tf32r(a.z), tf32r(b.z), tf32r(a.w), tf32r(b.w));
    *(float4*)(d + (size_t)i * 8)     = o0;
    *(float4*)(d + (size_t)i * 8 + 4) = o1;
}

// ===========================================================================
// C[M,N] = A[M,K] @ B[N,K]^T  (2048^3) via tf32 mma.sync, pre-rounded &
// K-group-permuted operands. CTA 128x128, BK=16, 8 warps, double-buffered
// cp.async, dynamic smem pitch 24 floats (12 float2, conflict-free LDS.64).
// blockIdx.z selects (B, C) -> fuses the Q/K/V projections into one launch.
// ===========================================================================
#define BK    16
#define LDS_P 24            // floats per smem row
#define P2    12            // float2 pitch
#define NTIL  (CH / BK)     // 128
#define GEMM_DSMEM (2 * 128 * LDS_P * 4 * 2)   // 49152 B

__global__ __launch_bounds__(256, 2) void mma_gemm_p(
    const float* __restrict__ A,
    const float* __restrict__ B0, const float* __restrict__ B1,
    const float* __restrict__ B2,
    float* __restrict__ C0, float* __restrict__ C1, float* __restrict__ C2) {
    extern __shared__ __align__(16) float gsm[];
    float* As = gsm;                           // [2][128][LDS_P]
    float* Bs = gsm + 2 * 128 * LDS_P;         // [2][128][LDS_P]

    const float* B = (blockIdx.z == 0) ? B0 : (blockIdx.z == 1) ? B1 : B2;
    float*       C = (blockIdx.z == 0) ? C0 : (blockIdx.z == 1) ? C1 : C2;

    const int tid  = threadIdx.x;
    const int lane = tid & 31;
    const int wid  = tid >> 5;
    const int wm   = (wid & 1) * 64;
    const int wn   = (wid >> 1) * 32;

    const int m0 = blockIdx.y * 128;
    const int n0 = blockIdx.x * 128;
    const float* Ab = A + (size_t)m0 * CH;
    const float* Bb = B + (size_t)n0 * CH;

    const uint32_t sA0 = smem_to_u32(As);
    const uint32_t sB0 = smem_to_u32(Bs);

    const int r0c = tid >> 2;              // 0..63
    const int c4  = (tid & 3) << 2;        // {0,4,8,12}

    float acc[4][4][4];
#pragma unroll
    for (int mt = 0; mt < 4; mt++)
#pragma unroll
        for (int nt = 0; nt < 4; nt++)
#pragma unroll
            for (int e = 0; e < 4; e++) acc[mt][nt][e] = 0.f;

#pragma unroll
    for (int i = 0; i < 2; i++) {
        int row = r0c + i * 64;
        uint32_t off = (uint32_t)(row * LDS_P + c4) * 4u;
        cp_async16(sA0 + off, Ab + (size_t)row * CH + c4);
        cp_async16(sB0 + off, Bb + (size_t)row * CH + c4);
    }
    CP_COMMIT();

    for (int kt = 0; kt < NTIL; kt++) {
        CP_WAIT0();
        __syncthreads();

        if (kt + 1 < NTIL) {
            const int nbuf = (kt + 1) & 1;
            const int kc   = (kt + 1) * BK;
            const uint32_t sAd = sA0 + (uint32_t)(nbuf * 128 * LDS_P * 4);
            const uint32_t sBd = sB0 + (uint32_t)(nbuf * 128 * LDS_P * 4);
#pragma unroll
            for (int i = 0; i < 2; i++) {
                int row = r0c + i * 64;
                uint32_t off = (uint32_t)(row * LDS_P + c4) * 4u;
                cp_async16(sAd + off, Ab + (size_t)row * CH + kc + c4);
                cp_async16(sBd + off, Bb + (size_t)row * CH + kc + c4);
            }
            CP_COMMIT();
        }

        const int buf = kt & 1;
        const float2* Asb = (const float2*)(As + buf * 128 * LDS_P);
        const float2* Bsb = (const float2*)(Bs + buf * 128 * LDS_P);
#pragma unroll
        for (int ks = 0; ks < 2; ks++) {
            const int jq = ks * 4 + (lane & 3);
            uint32_t af[4][4], bf[4][2];
#pragma unroll
            for (int mt = 0; mt < 4; mt++) {
                int r = wm + mt * 16 + (lane >> 2);
                float2 f0 = Asb[r * P2 + jq];
                float2 f1 = Asb[(r + 8) * P2 + jq];
                af[mt][0] = __float_as_uint(f0.x);
                af[mt][1] = __float_as_uint(f1.x);
                af[mt][2] = __float_as_uint(f0.y);
                af[mt][3] = __float_as_uint(f1.y);
            }
#pragma unroll
            for (int nt = 0; nt < 4; nt++) {
                int cidx = wn + nt * 8 + (lane >> 2);
                float2 f = Bsb[cidx * P2 + jq];
                bf[nt][0] = __float_as_uint(f.x);
                bf[nt][1] = __float_as_uint(f.y);
            }
#pragma unroll
            for (int mt = 0; mt < 4; mt++)
#pragma unroll
                for (int nt = 0; nt < 4; nt++)
                    mma_tf32(acc[mt][nt], af[mt], bf[nt], acc[mt][nt]);
        }
        __syncthreads();
    }

#pragma unroll
    for (int mt = 0; mt < 4; mt++) {
        int r = m0 + wm + mt * 16 + (lane >> 2);
#pragma unroll
        for (int nt = 0; nt < 4; nt++) {
            int cidx = n0 + wn + nt * 8 + 2 * (lane & 3);
            *(float2*)(C + (size_t)r * CH + cidx) =
                make_float2(acc[mt][nt][0], acc[mt][nt][1]);
            *(float2*)(C + (size_t)(r + 8) * CH + cidx) =
                make_float2(acc[mt][nt][2], acc[mt][nt][3]);
        }
    }
}

// ---------------------------------------------------------------------------
// ReBased feature map (unchanged)
// ---------------------------------------------------------------------------
__global__ __launch_bounds__(256) void featmap(const float* __restrict__ gamma,
                                               const float* __restrict__ beta) {
    const int warp = threadIdx.x >> 5;
    const int lane = threadIdx.x & 31;
    const int row  = blockIdx.x * 8 + warp;
    float* base = (blockIdx.y == 0) ? g_q : g_k;
    const float scale = (blockIdx.y == 0) ? 0.08838834764831845f : 1.0f;
    const int t = row >> 4;
    const int h = row & 15;
    float* p = base + (size_t)t * CH + h * HD;

    float x[4];
    float s = 0.f, sq = 0.f;
#pragma unroll
    for (int r = 0; r < 4; r++) {
        int d = lane + 32 * r;
        float y = p[d] * gamma[d] + beta[d];
        x[r] = y;
        s  += y;
        sq += y * y;
    }
#pragma unroll
    for (int o = 16; o; o >>= 1) {
        s  += __shfl_xor_sync(0xFFFFFFFFu, s, o);
        sq += __shfl_xor_sync(0xFFFFFFFFu, sq, o);
    }
    const float mu  = s * (1.0f / HD);
    const float var = sq * (1.0f / HD) - mu * mu;
    const float rs  = rsqrtf(var + 1e-5f) * scale;
#pragma unroll
    for (int r = 0; r < 4; r++) p[lane + 32 * r] = (x[r] - mu) * rs;
}

// ===========================================================================
// Causal quadratic attention via tf32 mma.sync (verified R6):
//   S = q.k^T 3-pass split-tf32; S2 = masked S^2; z rowsum; O += S2 @ V tf32
// ===========================================================================
#define WQK 132
#define WVT 68
#define ATTN_SMEM2 (2 * 64 * WQK * 8 + 128 * WVT * 4 + 64 * WVT * 4 + 64 * 4)

__global__ __launch_bounds__(256, 1) void rebased_attn_mma() {
    extern __shared__ __align__(16) char dynsm[];
    float2* q_hl = (float2*)dynsm;                 // [64][WQK]
    float2* k_hl = q_hl + 64 * WQK;                // [64][WQK]
    float*  vt   = (float*)(k_hl + 64 * WQK);      // [128][WVT]
    float*  s2m  = vt + 128 * WVT;                 // [64][WVT]
    float*  zsh  = s2m + 64 * WVT;                 // [64]

    const int tid  = threadIdx.x;
    const int lane = tid & 31;
    const int wid  = tid >> 5;
    const int qt   = 31 - blockIdx.x;
    const int h    = blockIdx.y;
    const int q0   = qt * 64;

    const int wmQ = (wid & 1) * 32, wnQ = (wid >> 1) * 16;
    const int wmO = (wid & 1) * 32, wnO = (wid >> 1) * 32;

    {
        const int row = tid >> 2;
        const int cb  = (tid & 3) * 4;
        const float* src = g_q + (size_t)(q0 + row) * CH + h * HD;
        float2* dst = q_hl + row * WQK;
#pragma unroll
        for (int c = 0; c < 8; c++) {
            float4 x = *(const float4*)(src + c * 16 + cb);
            float xs[4] = {x.x, x.y, x.z, x.w};
#pragma unroll
            for (int i = 0; i < 4; i++) {
                float hi = tf32r(xs[i]);
                float lo = tf32r(xs[i] - hi);
                dst[c * 16 + cb + i] = make_float2(hi, lo);
            }
        }
    }
    if (tid < 64) zsh[tid] = 0.f;

    float oacc[2][4][4];
#pragma unroll
    for (int mt = 0; mt < 2; mt++)
#pragma unroll
        for (int nt = 0; nt < 4; nt++)
#pragma unroll
            for (int e = 0; e < 4; e++) oacc[mt][nt][e] = 0.f;

    for (int kt = 0; kt <= qt; kt++) {
        const int k0 = kt * 64;
        __syncthreads();

        {
            const int row = tid >> 2;
            const int cb  = (tid & 3) * 4;
            const float* src = g_k + (size_t)(k0 + row) * CH + h * HD;
            float2* dst = k_hl + row * WQK;
#pragma unroll
            for (int c = 0; c < 8; c++) {
                float4 x = *(const float4*)(src + c * 16 + cb);
                float xs[4] = {x.x, x.y, x.z, x.w};
#pragma unroll
                for (int i = 0; i < 4; i++) {
                    float hi = tf32r(xs[i]);
                    float lo = tf32r(xs[i] - hi);
                    dst[c * 16 + cb + i] = make_float2(hi, lo);
                }
            }
        }
        {
            const int jv = tid & 63;
            const int db = (tid >> 6) * 4;
            const float* src = g_v + (size_t)(k0 + jv) * CH + h * HD;
#pragma unroll
            for (int c = 0; c < 8; c++) {
                int d0 = db + c * 16;
                float4 x = *(const float4*)(src + d0);
                vt[(d0 + 0) * WVT + jv] = tf32r(x.x);
                vt[(d0 + 1) * WVT + jv] = tf32r(x.y);
                vt[(d0 + 2) * WVT + jv] = tf32r(x.z);
                vt[(d0 + 3) * WVT + jv] = tf32r(x.w);
            }
        }
        __syncthreads();

        float sacc[2][2][4];
#pragma unroll
        for (int mt = 0; mt < 2; mt++)
#pragma unroll
            for (int nt = 0; nt < 2; nt++)
#pragma unroll
                for (int e = 0; e < 4; e++) sacc[mt][nt][e] = 0.f;

#pragma unroll 4
        for (int k8 = 0; k8 < 16; k8++) {
            const int kq = k8 * 8 + (lane & 3);
            float2 a[2][4], b[2][2];
#pragma unroll
            for (int mt = 0; mt < 2; mt++) {
                int r = wmQ + mt * 16 + (lane >> 2);
                a[mt][0] = q_hl[r * WQK + kq];
                a[mt][1] = q_hl[(r + 8) * WQK + kq];
                a[mt][2] = q_hl[r * WQK + kq + 4];
                a[mt][3] = q_hl[(r + 8) * WQK + kq + 4];
            }
#pragma unroll
            for (int nt = 0; nt < 2; nt++) {
                int n = wnQ + nt * 8 + (lane >> 2);
                b[nt][0] = k_hl[n * WQK + kq];
                b[nt][1] = k_hl[n * WQK + kq + 4];
            }
#pragma unroll
            for (int mt = 0; mt < 2; mt++) {
                uint32_t ah[4] = {__float_as_uint(a[mt][0].x), __float_as_uint(a[mt][1].x),
                                  __float_as_uint(a[mt][2].x), __float_as_uint(a[mt][3].x)};
                uint32_t al[4] = {__float_as_uint(a[mt][0].y), __float_as_uint(a[mt][1].y),
                                  __float_as_uint(a[mt][2].y), __float_as_uint(a[mt][3].y)};
#pragma unroll
                for (int nt = 0; nt < 2; nt++) {
                    uint32_t bh[2] = {__float_as_uint(b[nt][0].x), __float_as_uint(b[nt][1].x)};
                    uint32_t bl[2] = {__float_as_uint(b[nt][0].y), __float_as_uint(b[nt][1].y)};
                    mma_tf32(sacc[mt][nt], ah, bh, sacc[mt][nt]);
                    mma_tf32(sacc[mt][nt], ah, bl, sacc[mt][nt]);
                    mma_tf32(sacc[mt][nt], al, bh, sacc[mt][nt]);
                }
            }
        }

        const bool diag = (kt == qt);
#pragma unroll
        for (int mt = 0; mt < 2; mt++) {
            const int r0l = wmQ + mt * 16 + (lane >> 2);
            float zp0 = 0.f, zp1 = 0.f;
#pragma unroll
            for (int nt = 0; nt < 2; nt++) {
                const int c0l = wnQ + nt * 8 + 2 * (lane & 3);
                float s0 = sacc[mt][nt][0]; s0 *= s0;
                float s1 = sacc[mt][nt][1]; s1 *= s1;
                float s2 = sacc[mt][nt][2]; s2 *= s2;
                float s3 = sacc[mt][nt][3]; s3 *= s3;
                if (diag) {
                    if (c0l > r0l)         s0 = 0.f;
                    if (c0l + 1 > r0l)     s1 = 0.f;
                    if (c0l > r0l + 8)     s2 = 0.f;
                    if (c0l + 1 > r0l + 8) s3 = 0.f;
                }
                *(float2*)&s2m[r0l * WVT + c0l]       = make_float2(s0, s1);
                *(float2*)&s2m[(r0l + 8) * WVT + c0l] = make_float2(s2, s3);
                zp0 += s0 + s1;
                zp1 += s2 + s3;
            }
            atomicAdd(&zsh[r0l], zp0);
            atomicAdd(&zsh[r0l + 8], zp1);
        }
        __syncthreads();

#pragma unroll 2
        for (int k8 = 0; k8 < 8; k8++) {
            const int kq = k8 * 8 + (lane & 3);
            uint32_t a[2][4];
#pragma unroll
            for (int mt = 0; mt < 2; mt++) {
                int r = wmO + mt * 16 + (lane >> 2);
                a[mt][0] = f2tf32(s2m[r * WVT + kq]);
                a[mt][1] = f2tf32(s2m[(r + 8) * WVT + kq]);
                a[mt][2] = f2tf32(s2m[r * WVT + kq + 4]);
                a[mt][3] = f2tf32(s2m[(r + 8) * WVT + kq + 4]);
            }
            uint32_t b[4][2];
#pragma unroll
            for (int nt = 0; nt < 4; nt++) {
                int n = wnO + nt * 8 + (lane >> 2);
                b[nt][0] = __float_as_uint(vt[n * WVT + kq]);
                b[nt][1] = __float_as_uint(vt[n * WVT + kq + 4]);
            }
#pragma unroll
            for (int mt = 0; mt < 2; mt++)
#pragma unroll
                for (int nt = 0; nt < 4; nt++)
                    mma_tf32(oacc[mt][nt], a[mt], b[nt], oacc[mt][nt]);
        }
    }
    __syncthreads();

#pragma unroll
    for (int mt = 0; mt < 2; mt++) {
        const int rl = wmO + mt * 16 + (lane >> 2);
        const float inv0 = 1.0f / (zsh[rl] + 1e-5f);
        const float inv1 = 1.0f / (zsh[rl + 8] + 1e-5f);
        float* o0 = g_o + (size_t)(q0 + rl) * CH + h * HD;
        float* o1 = g_o + (size_t)(q0 + rl + 8) * CH + h * HD;
#pragma unroll
        for (int nt = 0; nt < 4; nt++) {
            const int cl = wnO + nt * 8 + 2 * (lane & 3);
            *(float2*)(o0 + cl) = make_float2(oacc[mt][nt][0] * inv0,
                                              oacc[mt][nt][1] * inv0);
            *(float2*)(o1 + cl) = make_float2(oacc[mt][nt][2] * inv1,
                                              oacc[mt][nt][3] * inv1);
        }
    }
}

// ---------------------------------------------------------------------------
extern "C" void kernel_launch(void* const* d_in, const int* in_sizes, int n_in,
                              void* d_out, int out_size) {
    const float* X     = (const float*)d_in[0];
    const float* Wq    = (const float*)d_in[1];
    const float* Wk    = (const float*)d_in[2];
    const float* Wv    = (const float*)d_in[3];
    const float* Wo    = (const float*)d_in[4];
    const float* gamma = (const float*)d_in[5];
    const float* beta  = (const float*)d_in[6];
    float* out = (float*)d_out;

    float *q, *k, *v, *o, *xp, *wqp, *wkp, *wvp, *wop, *op;
    cudaGetSymbolAddress((void**)&q, g_q);
    cudaGetSymbolAddress((void**)&k, g_k);
    cudaGetSymbolAddress((void**)&v, g_v);
    cudaGetSymbolAddress((void**)&o, g_o);
    cudaGetSymbolAddress((void**)&xp, g_xp);
    cudaGetSymbolAddress((void**)&wqp, g_wqp);
    cudaGetSymbolAddress((void**)&wkp, g_wkp);
    cudaGetSymbolAddress((void**)&wvp, g_wvp);
    cudaGetSymbolAddress((void**)&wop, g_wop);
    cudaGetSymbolAddress((void**)&op, g_op);

    cudaFuncSetAttribute(rebased_attn_mma,
                         cudaFuncAttributeMaxDynamicSharedMemorySize, ATTN_SMEM2);
    cudaFuncSetAttribute(mma_gemm_p,
                         cudaFuncAttributeMaxDynamicSharedMemorySize, GEMM_DSMEM);

    dim3 b256(256);
    const int NGRP = TSEQ * CH / 8;   // 8-float groups per matrix

    // pre-round + K-group permute: X, Wq, Wk, Wv, Wo
    round_permute5<<<dim3(NGRP / 256, 5), b256>>>(
        X, Wq, Wk, Wv, Wo, xp, wqp, wkp, wvp, wop, 5);

    // fused Q/K/V projections
    mma_gemm_p<<<dim3(16, 16, 3), b256, GEMM_DSMEM>>>(
        xp, wqp, wkp, wvp, q, k, v);

    // feature map (q scaled by D^-0.5, k unscaled)
    featmap<<<dim3(TSEQ * NH / 8, 2), b256>>>(gamma, beta);

    // causal quadratic attention (tf32 mma, split-tf32 scores)
    rebased_attn_mma<<<dim3(TSEQ / 64, NH), b256, ATTN_SMEM2>>>();

    // round+permute attention output, then O projection
    round_permute5<<<dim3(NGRP / 256, 1), b256>>>(
        o, o, o, o, o, op, op, op, op, op, 1);
    mma_gemm_p<<<dim3(16, 16, 1), b256, GEMM_DSMEM>>>(
        op, wop, wop, wop, out, out, out);
}